// round 1
// baseline (speedup 1.0000x reference)
#include <cuda_runtime.h>
#include <cuda_fp16.h>
#include <cstdint>

// Problem constants
#define TT 256
#define BB 16
#define HH 2048
#define LL 3
#define VV 32000
#define TB (TT*BB)       // 4096
#define H4 (4*HH)        // 8192

// ---------------------------------------------------------------------------
// Static device scratch (no runtime allocation allowed)
// ---------------------------------------------------------------------------
__device__ __half g_wih16[(size_t)LL*H4*HH];     // 100 MB
__device__ __half g_whh16[(size_t)LL*H4*HH];     // 100 MB
__device__ __half g_watt16[(size_t)HH*2*HH];     // 16.8 MB
__device__ __half g_decw16[(size_t)VV*HH];       // 131 MB
__device__ __half g_x16[(size_t)TB*HH];          // embeddings fp16
__device__ float  g_gin[(size_t)TB*H4];          // 134 MB input-proj gates
__device__ __half g_hs16[(size_t)TB*HH];         // hidden states fp16 (reused per layer)
__device__ float  g_hs32[(size_t)TB*HH];         // hidden states fp32 (last layer survives)
__device__ float  g_c[BB*HH];
__device__ __half g_h0_16[BB*HH];
__device__ float  g_scores[(size_t)TT*BB*TT];
__device__ __half g_attn16[(size_t)TT*BB*TT];
__device__ __half g_hsT16[(size_t)BB*HH*TT];
__device__ float  g_ctx32[(size_t)TB*HH];
__device__ __half g_ctx16[(size_t)TB*HH];
__device__ float  g_att32[(size_t)TB*HH];
__device__ __half g_att16[(size_t)TB*HH];

// ---------------------------------------------------------------------------
// Helpers
// ---------------------------------------------------------------------------
__device__ __forceinline__ void cp_async8(void* sm, const void* gm) {
    unsigned saddr = (unsigned)__cvta_generic_to_shared(sm);
    asm volatile("cp.async.ca.shared.global [%0], [%1], 8;\n" :: "r"(saddr), "l"(gm));
}
__device__ __forceinline__ void cp_commit() {
    asm volatile("cp.async.commit_group;\n");
}
template<int N>
__device__ __forceinline__ void cp_wait() {
    asm volatile("cp.async.wait_group %0;\n" :: "n"(N));
}

__device__ __forceinline__ void mma_16816(float& d0, float& d1, float& d2, float& d3,
                                          uint32_t a0, uint32_t a1, uint32_t a2, uint32_t a3,
                                          uint32_t b0, uint32_t b1) {
    asm volatile(
        "mma.sync.aligned.m16n8k16.row.col.f32.f16.f16.f32 "
        "{%0,%1,%2,%3}, {%4,%5,%6,%7}, {%8,%9}, {%0,%1,%2,%3};\n"
        : "+f"(d0), "+f"(d1), "+f"(d2), "+f"(d3)
        : "r"(a0), "r"(a1), "r"(a2), "r"(a3), "r"(b0), "r"(b1));
}

__device__ __forceinline__ float sigmoidf_(float x) { return 1.f / (1.f + expf(-x)); }

// ---------------------------------------------------------------------------
// f32 -> f16 conversion (n must be a multiple of 4)
// ---------------------------------------------------------------------------
__global__ void f32_to_f16(const float* __restrict__ src, __half* __restrict__ dst, long n) {
    long i = ((long)blockIdx.x * blockDim.x + threadIdx.x) * 4;
    if (i + 3 < n) {
        float4 v = *(const float4*)(src + i);
        __half2 h0 = __floats2half2_rn(v.x, v.y);
        __half2 h1 = __floats2half2_rn(v.z, v.w);
        *(__half2*)(dst + i)     = h0;
        *(__half2*)(dst + i + 2) = h1;
    }
}

__global__ void copy_f32(const float* __restrict__ s, float* __restrict__ d, int n) {
    int i = blockIdx.x * blockDim.x + threadIdx.x;
    if (i < n) d[i] = s[i];
}

// ---------------------------------------------------------------------------
// Embedding gather: x16[tok,:] = fp16(emb_W[ids[tok],:])
// ---------------------------------------------------------------------------
__global__ void embed_gather(const int* __restrict__ ids, const float* __restrict__ emb,
                             __half* __restrict__ x16) {
    int tok = blockIdx.x;                    // t*B+b
    int id  = ids[tok];
    const float4* src = (const float4*)(emb + (size_t)id * HH);
    __half* dst = x16 + (size_t)tok * HH;
    for (int i = threadIdx.x; i < HH / 4; i += blockDim.x) {
        float4 v = src[i];
        *(__half2*)(dst + i * 4)     = __floats2half2_rn(v.x, v.y);
        *(__half2*)(dst + i * 4 + 2) = __floats2half2_rn(v.z, v.w);
    }
}

// ---------------------------------------------------------------------------
// Generic fp16 GEMM: C[m,n] (+=) sum_k A[m,k]*B[n,k] (+bias[n]) (tanh)
// Tiles: BM=128, BN=128, BK=32, 256 threads (8 warps as 2m x 4n), double-buffered
// Requires M%128==0, N%128==0, K%32==0 (true for all uses here).
// ---------------------------------------------------------------------------
template<bool BIAS, bool ACCUM, bool TANH>
__global__ void __launch_bounds__(256) gemm_tc(
    float* __restrict__ C, const __half* __restrict__ A, const __half* __restrict__ B,
    const float* __restrict__ bias,
    int M, int N, int K, long lda, long ldb, long ldc,
    long bsA, long bsB, long bsC)
{
    __shared__ __half As[2][128][40];
    __shared__ __half Bs[2][128][40];

    int tid = threadIdx.x, lane = tid & 31, w = tid >> 5;
    int wm = w & 1, wn = w >> 1;
    int mtile = blockIdx.y, ntile = blockIdx.x, z = blockIdx.z;

    const __half* Ab = A + (size_t)z * bsA + (size_t)mtile * 128 * lda;
    const __half* Bb = B + (size_t)z * bsB + (size_t)ntile * 128 * ldb;

    float acc[4][4][4];
#pragma unroll
    for (int mi = 0; mi < 4; mi++)
#pragma unroll
        for (int ni = 0; ni < 4; ni++)
#pragma unroll
            for (int q = 0; q < 4; q++) acc[mi][ni][q] = 0.f;

    const int KT = K / 32;

    // loader: tile = 128 rows x 32 halfs = 1024 x 8B chunks per matrix; 4 per thread
#define LOAD_TILE(kt, st)                                                          \
    {                                                                              \
        const __half* Ag = Ab + (kt) * 32;                                         \
        const __half* Bg = Bb + (kt) * 32;                                         \
        _Pragma("unroll")                                                          \
        for (int i_ = 0; i_ < 4; i_++) {                                           \
            int c_ = tid + i_ * 256;                                               \
            int row_ = c_ >> 3, off_ = (c_ & 7) * 4;                               \
            cp_async8(&As[st][row_][off_], Ag + (size_t)row_ * lda + off_);        \
            cp_async8(&Bs[st][row_][off_], Bg + (size_t)row_ * ldb + off_);        \
        }                                                                          \
        cp_commit();                                                               \
    }

    LOAD_TILE(0, 0);

    for (int kt = 0; kt < KT; ++kt) {
        int st = kt & 1;
        if (kt + 1 < KT) {
            LOAD_TILE(kt + 1, st ^ 1);
            cp_wait<1>();
        } else {
            cp_wait<0>();
        }
        __syncthreads();

#pragma unroll
        for (int kk = 0; kk < 2; kk++) {
            int kb = kk * 16;
            int kp = (lane & 3) * 2;
            int ar = lane >> 2;
            uint32_t afr[4][4];
#pragma unroll
            for (int mi = 0; mi < 4; mi++) {
                int r = wm * 64 + mi * 16 + ar;
                afr[mi][0] = *(const uint32_t*)&As[st][r][kb + kp];
                afr[mi][1] = *(const uint32_t*)&As[st][r + 8][kb + kp];
                afr[mi][2] = *(const uint32_t*)&As[st][r][kb + kp + 8];
                afr[mi][3] = *(const uint32_t*)&As[st][r + 8][kb + kp + 8];
            }
            uint32_t bfr[4][2];
#pragma unroll
            for (int ni = 0; ni < 4; ni++) {
                int rb = wn * 32 + ni * 8 + ar;
                bfr[ni][0] = *(const uint32_t*)&Bs[st][rb][kb + kp];
                bfr[ni][1] = *(const uint32_t*)&Bs[st][rb][kb + kp + 8];
            }
#pragma unroll
            for (int mi = 0; mi < 4; mi++)
#pragma unroll
                for (int ni = 0; ni < 4; ni++)
                    mma_16816(acc[mi][ni][0], acc[mi][ni][1], acc[mi][ni][2], acc[mi][ni][3],
                              afr[mi][0], afr[mi][1], afr[mi][2], afr[mi][3],
                              bfr[ni][0], bfr[ni][1]);
        }
        __syncthreads();
    }
#undef LOAD_TILE

    // epilogue
    float* Cp = C + (size_t)z * bsC;
#pragma unroll
    for (int mi = 0; mi < 4; mi++) {
        int r0 = mtile * 128 + wm * 64 + mi * 16 + (lane >> 2);
        int r1 = r0 + 8;
#pragma unroll
        for (int ni = 0; ni < 4; ni++) {
            int col = ntile * 128 + wn * 32 + ni * 8 + (lane & 3) * 2;
            size_t i0 = (size_t)r0 * ldc + col;
            size_t i1 = (size_t)r1 * ldc + col;
            float2 v01 = make_float2(acc[mi][ni][0], acc[mi][ni][1]);
            float2 v23 = make_float2(acc[mi][ni][2], acc[mi][ni][3]);
            if (ACCUM) {
                float2 o0 = *(const float2*)&Cp[i0];
                float2 o1 = *(const float2*)&Cp[i1];
                v01.x += o0.x; v01.y += o0.y; v23.x += o1.x; v23.y += o1.y;
            }
            if (BIAS) {
                float b0 = bias[col], b1 = bias[col + 1];
                v01.x += b0; v01.y += b1; v23.x += b0; v23.y += b1;
            }
            if (TANH) {
                v01.x = tanhf(v01.x); v01.y = tanhf(v01.y);
                v23.x = tanhf(v23.x); v23.y = tanhf(v23.y);
            }
            *(float2*)&Cp[i0] = v01;
            *(float2*)&Cp[i1] = v23;
        }
    }
}

// ---------------------------------------------------------------------------
// LSTM recurrent step: 128 CTAs, each owns 16 hidden units.
// CTA blk computes R = h_prev @ Whh^T for cols {g*2048 + blk*16 + u : g<4, u<16},
// adds precomputed Gin (incl. bias), applies the cell, writes h (f16+f32) and c.
// ---------------------------------------------------------------------------
__global__ void __launch_bounds__(256) lstm_step(
    const __half* __restrict__ hprev,   // [16,2048] f16
    float* __restrict__ cbuf,           // [16,2048] f32
    const float* __restrict__ gin_t,    // [16,8192] f32 (incl. bias)
    const __half* __restrict__ whh,     // [8192,2048] f16
    __half* __restrict__ hout16,        // [16,2048]
    float* __restrict__ hout32)         // [16,2048]
{
    __shared__ __half As[16][72];
    __shared__ __half Bs[64][72];
    __shared__ float  Rs[16][64];

    int tid = threadIdx.x, lane = tid & 31, w = tid >> 5;
    int blk = blockIdx.x;
    int g = w >> 1, hf = w & 1;

    float a0 = 0.f, a1 = 0.f, a2 = 0.f, a3 = 0.f;

    // loaders
    const int rlB = tid >> 2;            // 0..63
    const int kB  = (tid & 3) * 16;      // 0,16,32,48
    const int gr  = rlB >> 4, uB = rlB & 15;
    const __half* Bgp = whh + (size_t)(gr * HH + blk * 16 + uB) * HH + kB;
    const int rA = tid >> 4;             // 0..15
    const int kA = (tid & 15) * 4;       // 0..60
    const __half* Agp = hprev + (size_t)rA * HH + kA;

    uint4 breg0 = *(const uint4*)(Bgp);
    uint4 breg1 = *(const uint4*)(Bgp + 8);
    uint2 areg  = *(const uint2*)(Agp);

    for (int it = 0; it < HH / 64; ++it) {
        __syncthreads();
        *(uint4*)&Bs[rlB][kB]     = breg0;
        *(uint4*)&Bs[rlB][kB + 8] = breg1;
        *(uint2*)&As[rA][kA]      = areg;
        __syncthreads();
        if (it + 1 < HH / 64) {
            int k0 = (it + 1) * 64;
            breg0 = *(const uint4*)(Bgp + k0);
            breg1 = *(const uint4*)(Bgp + k0 + 8);
            areg  = *(const uint2*)(Agp + k0);
        }
#pragma unroll
        for (int kk = 0; kk < 4; kk++) {
            int kb = kk * 16;
            int arow = lane >> 2, kp = (lane & 3) * 2;
            uint32_t fa0 = *(const uint32_t*)&As[arow][kb + kp];
            uint32_t fa1 = *(const uint32_t*)&As[arow + 8][kb + kp];
            uint32_t fa2 = *(const uint32_t*)&As[arow][kb + kp + 8];
            uint32_t fa3 = *(const uint32_t*)&As[arow + 8][kb + kp + 8];
            int brow = g * 16 + hf * 8 + (lane >> 2);
            uint32_t fb0 = *(const uint32_t*)&Bs[brow][kb + kp];
            uint32_t fb1 = *(const uint32_t*)&Bs[brow][kb + kp + 8];
            mma_16816(a0, a1, a2, a3, fa0, fa1, fa2, fa3, fb0, fb1);
        }
    }
    __syncthreads();
    {
        int r0 = lane >> 2, cp = (lane & 3) * 2;
        int cl = g * 16 + hf * 8 + cp;
        Rs[r0][cl] = a0;     Rs[r0][cl + 1] = a1;
        Rs[r0 + 8][cl] = a2; Rs[r0 + 8][cl + 1] = a3;
    }
    __syncthreads();

    // LSTM cell: one thread per (batch row r, unit u)
    int r = tid >> 4, u = tid & 15;
    int col = blk * 16 + u;
    float gi = Rs[r][u]      + gin_t[(size_t)r * H4 + col];
    float gf = Rs[r][16 + u] + gin_t[(size_t)r * H4 + HH + col];
    float gg = Rs[r][32 + u] + gin_t[(size_t)r * H4 + 2 * HH + col];
    float go = Rs[r][48 + u] + gin_t[(size_t)r * H4 + 3 * HH + col];
    float co = cbuf[(size_t)r * HH + col];
    float cn = sigmoidf_(gf) * co + sigmoidf_(gi) * tanhf(gg);
    float h  = sigmoidf_(go) * tanhf(cn);
    cbuf[(size_t)r * HH + col]   = cn;
    hout32[(size_t)r * HH + col] = h;
    hout16[(size_t)r * HH + col] = __float2half_rn(h);
}

// ---------------------------------------------------------------------------
// Causal softmax: one block per (t,b) row of 256 scores -> attn f16
// ---------------------------------------------------------------------------
__global__ void softmax_causal(const float* __restrict__ scores, __half* __restrict__ attn) {
    int row = blockIdx.x;            // t*16+b
    int t = row >> 4;
    const float* sp = scores + (size_t)row * TT;
    __half* ap = attn + (size_t)row * TT;
    int s = threadIdx.x;
    const float inv = 0.022097086912079608f; // 1/sqrt(2048)
    float v = (s <= t) ? sp[s] * inv : -1e30f;
    __shared__ float red[256];
    red[s] = v; __syncthreads();
    for (int o = 128; o > 0; o >>= 1) { if (s < o) red[s] = fmaxf(red[s], red[s + o]); __syncthreads(); }
    float m = red[0]; __syncthreads();
    float e = (s <= t) ? expf(v - m) : 0.f;
    red[s] = e; __syncthreads();
    for (int o = 128; o > 0; o >>= 1) { if (s < o) red[s] += red[s + o]; __syncthreads(); }
    float sum = red[0];
    ap[s] = __float2half_rn(e / sum);
}

// ---------------------------------------------------------------------------
// Transpose hs[t][b][h] -> hsT[b][h][t] (f16 -> f16)
// ---------------------------------------------------------------------------
__global__ void transpose_hs(const __half* __restrict__ hs, __half* __restrict__ hsT) {
    long i = (long)blockIdx.x * blockDim.x + threadIdx.x;   // over b,h,t (t fastest)
    if (i >= (long)BB * HH * TT) return;
    int t = i & (TT - 1);
    long r = i >> 8;
    int h = r & (HH - 1);
    int b = (int)(r >> 11);
    hsT[i] = hs[(size_t)t * (BB * HH) + (size_t)b * HH + h];
}

// ---------------------------------------------------------------------------
// Host driver
// ---------------------------------------------------------------------------
extern "C" void kernel_launch(void* const* d_in, const int* in_sizes, int n_in,
                              void* d_out, int out_size) {
    const int*   ids  = (const int*)d_in[0];
    const float* h0   = (const float*)d_in[1];
    const float* c0   = (const float*)d_in[2];
    const float* embW = (const float*)d_in[3];
    const float* Wih  = (const float*)d_in[4];
    const float* Whh  = (const float*)d_in[5];
    const float* bvec = (const float*)d_in[6];
    const float* Watt = (const float*)d_in[7];
    const float* batt = (const float*)d_in[8];
    const float* decW = (const float*)d_in[9];
    const float* decb = (const float*)d_in[10];
    float* out = (float*)d_out;

    __half *wih16, *whh16, *watt16, *decw16, *x16, *hs16, *h016, *attn16, *hsT16, *ctx16, *att16;
    float *gin, *hs32, *cbuf, *scores, *ctx32, *att32;
    cudaGetSymbolAddress((void**)&wih16,  g_wih16);
    cudaGetSymbolAddress((void**)&whh16,  g_whh16);
    cudaGetSymbolAddress((void**)&watt16, g_watt16);
    cudaGetSymbolAddress((void**)&decw16, g_decw16);
    cudaGetSymbolAddress((void**)&x16,    g_x16);
    cudaGetSymbolAddress((void**)&gin,    g_gin);
    cudaGetSymbolAddress((void**)&hs16,   g_hs16);
    cudaGetSymbolAddress((void**)&hs32,   g_hs32);
    cudaGetSymbolAddress((void**)&cbuf,   g_c);
    cudaGetSymbolAddress((void**)&h016,   g_h0_16);
    cudaGetSymbolAddress((void**)&scores, g_scores);
    cudaGetSymbolAddress((void**)&attn16, g_attn16);
    cudaGetSymbolAddress((void**)&hsT16,  g_hsT16);
    cudaGetSymbolAddress((void**)&ctx32,  g_ctx32);
    cudaGetSymbolAddress((void**)&ctx16,  g_ctx16);
    cudaGetSymbolAddress((void**)&att32,  g_att32);
    cudaGetSymbolAddress((void**)&att16,  g_att16);

    const long nWih = (long)LL * H4 * HH;          // 50331648
    const long nWatt = (long)HH * 2 * HH;          // 8388608
    const long nDec = (long)VV * HH;               // 65536000

    // weight conversions
    f32_to_f16<<<(unsigned)(nWih / 1024), 256>>>(Wih,  wih16, nWih);
    f32_to_f16<<<(unsigned)(nWih / 1024), 256>>>(Whh,  whh16, nWih);
    f32_to_f16<<<(unsigned)(nWatt / 1024), 256>>>(Watt, watt16, nWatt);
    f32_to_f16<<<(unsigned)(nDec / 1024), 256>>>(decW, decw16, nDec);

    // embedding
    embed_gather<<<TB, 256>>>(ids, embW, x16);

    const long layerW = (long)H4 * HH;             // 16777216

    for (int l = 0; l < LL; l++) {
        const __half* xin = (l == 0) ? x16 : hs16;
        // Gin = X @ Wih_l^T + b_l   : [4096, 8192]
        gemm_tc<true, false, false><<<dim3(H4 / 128, TB / 128, 1), 256>>>(
            gin, xin, wih16 + (size_t)l * layerW, bvec + (size_t)l * H4,
            TB, H4, HH, HH, HH, H4, 0, 0, 0);
        // init h,c
        f32_to_f16<<<BB * HH / 1024, 256>>>(h0 + (size_t)l * BB * HH, h016, BB * HH);
        copy_f32<<<(BB * HH + 255) / 256, 256>>>(c0 + (size_t)l * BB * HH, cbuf, BB * HH);
        // recurrence
        for (int t = 0; t < TT; t++) {
            const __half* hp = (t == 0) ? h016 : (hs16 + (size_t)(t - 1) * BB * HH);
            lstm_step<<<HH / 16, 256>>>(
                hp, cbuf, gin + (size_t)t * BB * H4, whh16 + (size_t)l * layerW,
                hs16 + (size_t)t * BB * HH, hs32 + (size_t)t * BB * HH);
        }
    }

    // attention scores: per-batch [256,256] = hs @ hs^T (K=2048)
    gemm_tc<false, false, false><<<dim3(2, 2, BB), 256>>>(
        scores, hs16, hs16, nullptr,
        TT, TT, HH, (long)BB * HH, (long)BB * HH, (long)BB * TT,
        HH, HH, TT);

    softmax_causal<<<TB, 256>>>(scores, attn16);

    transpose_hs<<<(unsigned)((long)BB * HH * TT / 256), 256>>>(hs16, hsT16);

    // ctx = attn @ hs (per batch): M=256, N=2048, K=256
    gemm_tc<false, false, false><<<dim3(HH / 128, 2, BB), 256>>>(
        ctx32, attn16, hsT16, nullptr,
        TT, HH, TT, (long)BB * TT, TT, (long)BB * HH,
        TT, (long)HH * TT, HH);

    f32_to_f16<<<(unsigned)((long)TB * HH / 1024), 256>>>(ctx32, ctx16, (long)TB * HH);

    // out = tanh(hs @ W1^T + ctx @ W2^T + b_att)
    gemm_tc<false, false, false><<<dim3(HH / 128, TB / 128, 1), 256>>>(
        att32, hs16, watt16, nullptr,
        TB, HH, HH, HH, 2 * HH, HH, 0, 0, 0);
    gemm_tc<true, true, true><<<dim3(HH / 128, TB / 128, 1), 256>>>(
        att32, ctx16, watt16 + HH, batt,
        TB, HH, HH, HH, 2 * HH, HH, 0, 0, 0);

    f32_to_f16<<<(unsigned)((long)TB * HH / 1024), 256>>>(att32, att16, (long)TB * HH);

    // decode: [4096, 32000]
    gemm_tc<true, false, false><<<dim3(VV / 128, TB / 128, 1), 256>>>(
        out, att16, decw16, decb,
        TB, VV, HH, HH, HH, VV, 0, 0, 0);
}

// round 3
// speedup vs baseline: 1.3763x; 1.3763x over previous
#include <cuda_runtime.h>
#include <cuda_fp16.h>
#include <cstdint>

// Problem constants
#define TT 256
#define BB 16
#define HH 2048
#define LL 3
#define VV 32000
#define TB (TT*BB)       // 4096
#define H4 (4*HH)        // 8192
#define NCTA 128

// ---------------------------------------------------------------------------
// Static device scratch
// ---------------------------------------------------------------------------
__device__ __half g_wih16[(size_t)LL*H4*HH];
__device__ __half g_whh16[(size_t)LL*H4*HH];
__device__ __half g_watt16[(size_t)HH*2*HH];
__device__ __half g_decw16[(size_t)VV*HH];
__device__ __half g_x16[(size_t)TB*HH];
__device__ float  g_gin[(size_t)TB*H4];
__device__ __half g_hs16[(size_t)TB*HH];
__device__ __half g_h0_16[BB*HH];
__device__ float  g_scores[(size_t)TT*BB*TT];
__device__ __half g_attn16[(size_t)TT*BB*TT];
__device__ __half g_hsT16[(size_t)BB*HH*TT];
__device__ float  g_ctx32[(size_t)TB*HH];
__device__ __half g_ctx16[(size_t)TB*HH];
__device__ float  g_att32[(size_t)TB*HH];
__device__ __half g_att16[(size_t)TB*HH];
__device__ unsigned g_bar_cnt = 0;
__device__ unsigned g_bar_gen = 0;

// ---------------------------------------------------------------------------
// Helpers
// ---------------------------------------------------------------------------
__device__ __forceinline__ void cp_async16(void* sm, const void* gm) {
    unsigned saddr = (unsigned)__cvta_generic_to_shared(sm);
    asm volatile("cp.async.cg.shared.global [%0], [%1], 16;\n" :: "r"(saddr), "l"(gm));
}
__device__ __forceinline__ void cp_commit() {
    asm volatile("cp.async.commit_group;\n");
}
template<int N>
__device__ __forceinline__ void cp_wait() {
    asm volatile("cp.async.wait_group %0;\n" :: "n"(N));
}
__device__ __forceinline__ void ldsm_x4(uint32_t& r0, uint32_t& r1, uint32_t& r2, uint32_t& r3,
                                        const void* p) {
    unsigned a = (unsigned)__cvta_generic_to_shared(p);
    asm volatile("ldmatrix.sync.aligned.m8n8.x4.shared.b16 {%0,%1,%2,%3}, [%4];\n"
                 : "=r"(r0), "=r"(r1), "=r"(r2), "=r"(r3) : "r"(a));
}
__device__ __forceinline__ void ldsm_x2(uint32_t& r0, uint32_t& r1, const void* p) {
    unsigned a = (unsigned)__cvta_generic_to_shared(p);
    asm volatile("ldmatrix.sync.aligned.m8n8.x2.shared.b16 {%0,%1}, [%2];\n"
                 : "=r"(r0), "=r"(r1) : "r"(a));
}
__device__ __forceinline__ void mma_16816(float& d0, float& d1, float& d2, float& d3,
                                          uint32_t a0, uint32_t a1, uint32_t a2, uint32_t a3,
                                          uint32_t b0, uint32_t b1) {
    asm volatile(
        "mma.sync.aligned.m16n8k16.row.col.f32.f16.f16.f32 "
        "{%0,%1,%2,%3}, {%4,%5,%6,%7}, {%8,%9}, {%0,%1,%2,%3};\n"
        : "+f"(d0), "+f"(d1), "+f"(d2), "+f"(d3)
        : "r"(a0), "r"(a1), "r"(a2), "r"(a3), "r"(b0), "r"(b1));
}
__device__ __forceinline__ float sigmoidf_(float x) { return 1.f / (1.f + expf(-x)); }

// Hardened grid barrier: all inter-CTA traffic is device-scope atomics.
__device__ __forceinline__ void grid_bar(unsigned* cnt, unsigned* gen) {
    __threadfence();
    __syncthreads();
    if (threadIdx.x == 0) {
        unsigned g = atomicAdd(gen, 0u);
        unsigned a = atomicAdd(cnt, 1u);
        if (a == NCTA - 1) {
            atomicExch(cnt, 0u);
            __threadfence();
            atomicAdd(gen, 1u);
        } else {
            while (atomicAdd(gen, 0u) == g) { __nanosleep(64); }
        }
    }
    __syncthreads();
    __threadfence();
}

// ---------------------------------------------------------------------------
// Small utility kernels
// ---------------------------------------------------------------------------
__global__ void f32_to_f16(const float* __restrict__ src, __half* __restrict__ dst, long n) {
    long i = ((long)blockIdx.x * blockDim.x + threadIdx.x) * 4;
    if (i + 3 < n) {
        float4 v = *(const float4*)(src + i);
        *(__half2*)(dst + i)     = __floats2half2_rn(v.x, v.y);
        *(__half2*)(dst + i + 2) = __floats2half2_rn(v.z, v.w);
    }
}

__global__ void embed_gather(const int* __restrict__ ids, const float* __restrict__ emb,
                             __half* __restrict__ x16) {
    int tok = blockIdx.x;
    int id  = ids[tok];
    const float4* src = (const float4*)(emb + (size_t)id * HH);
    __half* dst = x16 + (size_t)tok * HH;
    for (int i = threadIdx.x; i < HH / 4; i += blockDim.x) {
        float4 v = src[i];
        *(__half2*)(dst + i * 4)     = __floats2half2_rn(v.x, v.y);
        *(__half2*)(dst + i * 4 + 2) = __floats2half2_rn(v.z, v.w);
    }
}

// ---------------------------------------------------------------------------
// GEMM v2: C[m,n] (+=) sum_k A[m,k]*B[n,k] (+bias) (tanh)
// 128x128 tile, BK=64, 3-stage cp.async, ldmatrix-fed HMMA, 2 CTAs/SM.
// ---------------------------------------------------------------------------
#define GEMM_SMEM (3 * 2 * 128 * 72 * 2)   // 110592 bytes

template<bool BIAS, bool ACCUM, bool TANH>
__global__ void __launch_bounds__(256, 2) gemm_tc(
    float* __restrict__ C, const __half* __restrict__ A, const __half* __restrict__ B,
    const float* __restrict__ bias,
    int M, int N, int K, long lda, long ldb, long ldc,
    long bsA, long bsB, long bsC)
{
    extern __shared__ char smraw[];
    __half* sm = (__half*)smraw;
    const int SH = 128 * 72;

    int tid = threadIdx.x, lane = tid & 31, w = tid >> 5;
    int wm = w & 1, wn = w >> 1;
    int mtile = blockIdx.y, ntile = blockIdx.x, z = blockIdx.z;

    const __half* Ab = A + (size_t)z * bsA + (size_t)mtile * 128 * lda;
    const __half* Bb = B + (size_t)z * bsB + (size_t)ntile * 128 * ldb;

    float acc[4][4][4];
#pragma unroll
    for (int mi = 0; mi < 4; mi++)
#pragma unroll
        for (int ni = 0; ni < 4; ni++)
#pragma unroll
            for (int q = 0; q < 4; q++) acc[mi][ni][q] = 0.f;

    const int KT = K / 64;

    auto load = [&](int kt, int st) {
        __half* Asm = sm + st * 2 * SH;
        __half* Bsm = Asm + SH;
        const __half* Ag = Ab + (size_t)kt * 64;
        const __half* Bg = Bb + (size_t)kt * 64;
#pragma unroll
        for (int i = 0; i < 4; i++) {
            int c = tid + i * 256;
            int row = c >> 3, off = (c & 7) * 8;
            cp_async16(Asm + row * 72 + off, Ag + (size_t)row * lda + off);
            cp_async16(Bsm + row * 72 + off, Bg + (size_t)row * ldb + off);
        }
        cp_commit();
    };

    load(0, 0);
    if (KT > 1) load(1, 1);

    for (int kt = 0; kt < KT; ++kt) {
        int st = kt % 3;
        if (kt + 2 < KT) { load(kt + 2, (kt + 2) % 3); cp_wait<2>(); }
        else if (kt + 1 < KT) cp_wait<1>();
        else cp_wait<0>();
        __syncthreads();

        __half* Asm = sm + st * 2 * SH;
        __half* Bsm = Asm + SH;
#pragma unroll
        for (int kk = 0; kk < 4; kk++) {
            int kb = kk * 16;
            uint32_t afr[4][4];
#pragma unroll
            for (int mi = 0; mi < 4; mi++) {
                const __half* p = Asm + (wm * 64 + mi * 16 + (lane & 15)) * 72
                                  + kb + ((lane >> 4) & 1) * 8;
                ldsm_x4(afr[mi][0], afr[mi][1], afr[mi][2], afr[mi][3], p);
            }
            uint32_t bfr[4][2];
            int idx = lane >> 3;
#pragma unroll
            for (int pr = 0; pr < 2; pr++) {
                const __half* p = Bsm + (wn * 32 + pr * 16 + ((idx >> 1) & 1) * 8 + (lane & 7)) * 72
                                  + kb + (idx & 1) * 8;
                ldsm_x4(bfr[2 * pr][0], bfr[2 * pr][1], bfr[2 * pr + 1][0], bfr[2 * pr + 1][1], p);
            }
#pragma unroll
            for (int mi = 0; mi < 4; mi++)
#pragma unroll
                for (int ni = 0; ni < 4; ni++)
                    mma_16816(acc[mi][ni][0], acc[mi][ni][1], acc[mi][ni][2], acc[mi][ni][3],
                              afr[mi][0], afr[mi][1], afr[mi][2], afr[mi][3],
                              bfr[ni][0], bfr[ni][1]);
        }
        __syncthreads();
    }

    float* Cp = C + (size_t)z * bsC;
#pragma unroll
    for (int mi = 0; mi < 4; mi++) {
        int r0 = mtile * 128 + wm * 64 + mi * 16 + (lane >> 2);
        int r1 = r0 + 8;
#pragma unroll
        for (int ni = 0; ni < 4; ni++) {
            int col = ntile * 128 + wn * 32 + ni * 8 + (lane & 3) * 2;
            size_t i0 = (size_t)r0 * ldc + col;
            size_t i1 = (size_t)r1 * ldc + col;
            float2 v01 = make_float2(acc[mi][ni][0], acc[mi][ni][1]);
            float2 v23 = make_float2(acc[mi][ni][2], acc[mi][ni][3]);
            if (ACCUM) {
                float2 o0 = *(const float2*)&Cp[i0];
                float2 o1 = *(const float2*)&Cp[i1];
                v01.x += o0.x; v01.y += o0.y; v23.x += o1.x; v23.y += o1.y;
            }
            if (BIAS) {
                float b0 = bias[col], b1 = bias[col + 1];
                v01.x += b0; v01.y += b1; v23.x += b0; v23.y += b1;
            }
            if (TANH) {
                v01.x = tanhf(v01.x); v01.y = tanhf(v01.y);
                v23.x = tanhf(v23.x); v23.y = tanhf(v23.y);
            }
            *(float2*)&Cp[i0] = v01;
            *(float2*)&Cp[i1] = v23;
        }
    }
}

// ---------------------------------------------------------------------------
// Persistent LSTM layer kernel (see round-2 comment block for layout).
// ---------------------------------------------------------------------------
#define LSTM_SMEM 224000

__global__ void __launch_bounds__(256, 1) lstm_layer_persist(
    const float* __restrict__ h0,
    const float* __restrict__ c0,
    const float* __restrict__ gin,
    const __half* __restrict__ whh,
    __half* __restrict__ hs16,
    __half* __restrict__ h016,
    unsigned* bar_cnt, unsigned* bar_gen)
{
    extern __shared__ char smraw[];
    __half* Bres = (__half*)smraw;                       // [48][2056] f16
    __half* As   = (__half*)(smraw + 197376);            // [2][2][16][72]
    __half* Bstg = (__half*)(smraw + 206592);            // [2][2][16][72]
    float*  Rs   = (float*)(smraw + 215808);             // [2][16][64] f32

    const int tid = threadIdx.x, lane = tid & 31, w = tid >> 5;
    const int rg = w & 3, ks = w >> 2;
    const int blk = blockIdx.x;

    // resident weight rows 0..47 (gates i,f,g)
    {
#pragma unroll
        for (int i = 0; i < 48; i++) {
            int c = tid + i * 256;
            int row = c >> 8, off = (c & 255) * 8;
            const __half* src = whh + (size_t)((row >> 4) * HH + blk * 16 + (row & 15)) * HH + off;
            cp_async16(Bres + (size_t)row * 2056 + off, src);
        }
        cp_commit();
    }

    // h0 conversion (grid covers exactly 16*2048)
    {
        int idx = blk * 256 + tid;
        h016[idx] = __float2half_rn(h0[idx]);
    }

    const int cr = tid >> 4, cu = tid & 15;
    const int ccol = blk * 16 + cu;
    float creg = c0[(size_t)cr * HH + ccol];

    grid_bar(bar_cnt, bar_gen);
    cp_wait<0>();
    __syncthreads();

    const int q = tid >> 7;
    const int lc = tid & 127;
    const int lrow = lc >> 3, loff = (lc & 7) * 8;
    const __half* sB = whh + (size_t)(3 * HH + blk * 16 + lrow) * HH + q * 1024 + loff;

    for (int t = 0; t < TT; ++t) {
        const __half* hp = t ? (hs16 + (size_t)(t - 1) * BB * HH) : h016;
        const float*  gin_t = gin + (size_t)t * BB * H4;

        auto load_chunk = [&](int it, int buf) {
            int base = (q * 2 + buf) * 16;
            cp_async16(As + (base + lrow) * 72 + loff,
                       hp + (size_t)lrow * HH + q * 1024 + it * 64 + loff);
            cp_async16(Bstg + (base + lrow) * 72 + loff, sB + it * 64);
            cp_commit();
        };

        float acc[2][4];
#pragma unroll
        for (int ni = 0; ni < 2; ni++)
#pragma unroll
            for (int qq = 0; qq < 4; qq++) acc[ni][qq] = 0.f;

        load_chunk(0, 0);
        for (int it = 0; it < 16; ++it) {
            int buf = it & 1;
            if (it < 15) { load_chunk(it + 1, buf ^ 1); cp_wait<1>(); }
            else cp_wait<0>();
            __syncthreads();

#pragma unroll
            for (int kk = 0; kk < 4; kk++) {
                int kb = kk * 16;
                uint32_t a0, a1, a2, a3;
                const __half* pa = As + ((ks * 2 + buf) * 16 + (lane & 15)) * 72
                                   + kb + ((lane >> 4) & 1) * 8;
                ldsm_x4(a0, a1, a2, a3, pa);
#pragma unroll
                for (int ni = 0; ni < 2; ni++) {
                    int row0 = rg * 16 + ni * 8;
                    const __half* pb;
                    if (rg < 3)
                        pb = Bres + (size_t)(row0 + (lane & 7)) * 2056
                             + ks * 1024 + it * 64 + kb + ((lane >> 3) & 1) * 8;
                    else
                        pb = Bstg + ((ks * 2 + buf) * 16 + ni * 8 + (lane & 7)) * 72
                             + kb + ((lane >> 3) & 1) * 8;
                    uint32_t b0, b1;
                    ldsm_x2(b0, b1, pb);
                    mma_16816(acc[ni][0], acc[ni][1], acc[ni][2], acc[ni][3],
                              a0, a1, a2, a3, b0, b1);
                }
            }
            __syncthreads();
        }

        {
            int r = lane >> 2;
#pragma unroll
            for (int ni = 0; ni < 2; ni++) {
                int cidx = rg * 16 + ni * 8 + (lane & 3) * 2;
                Rs[(ks * 16 + r) * 64 + cidx]         = acc[ni][0];
                Rs[(ks * 16 + r) * 64 + cidx + 1]     = acc[ni][1];
                Rs[(ks * 16 + r + 8) * 64 + cidx]     = acc[ni][2];
                Rs[(ks * 16 + r + 8) * 64 + cidx + 1] = acc[ni][3];
            }
        }
        __syncthreads();

        {
            const float* g0 = gin_t + (size_t)cr * H4;
            float gi = Rs[(cr) * 64 + cu]      + Rs[(16 + cr) * 64 + cu]      + g0[ccol];
            float gf = Rs[(cr) * 64 + 16 + cu] + Rs[(16 + cr) * 64 + 16 + cu] + g0[HH + ccol];
            float gg = Rs[(cr) * 64 + 32 + cu] + Rs[(16 + cr) * 64 + 32 + cu] + g0[2 * HH + ccol];
            float go = Rs[(cr) * 64 + 48 + cu] + Rs[(16 + cr) * 64 + 48 + cu] + g0[3 * HH + ccol];
            creg = sigmoidf_(gf) * creg + sigmoidf_(gi) * tanhf(gg);
            float h = sigmoidf_(go) * tanhf(creg);
            hs16[(size_t)t * BB * HH + (size_t)cr * HH + ccol] = __float2half_rn(h);
        }

        grid_bar(bar_cnt, bar_gen);
    }
}

// ---------------------------------------------------------------------------
// Causal softmax
// ---------------------------------------------------------------------------
__global__ void softmax_causal(const float* __restrict__ scores, __half* __restrict__ attn) {
    int row = blockIdx.x;
    int t = row >> 4;
    const float* sp = scores + (size_t)row * TT;
    __half* ap = attn + (size_t)row * TT;
    int s = threadIdx.x;
    const float inv = 0.022097086912079608f; // 1/sqrt(2048)
    float v = (s <= t) ? sp[s] * inv : -1e30f;
    __shared__ float red[256];
    red[s] = v; __syncthreads();
    for (int o = 128; o > 0; o >>= 1) { if (s < o) red[s] = fmaxf(red[s], red[s + o]); __syncthreads(); }
    float m = red[0]; __syncthreads();
    float e = (s <= t) ? expf(v - m) : 0.f;
    red[s] = e; __syncthreads();
    for (int o = 128; o > 0; o >>= 1) { if (s < o) red[s] += red[s + o]; __syncthreads(); }
    float sum = red[0];
    ap[s] = __float2half_rn(e / sum);
}

__global__ void transpose_hs(const __half* __restrict__ hs, __half* __restrict__ hsT) {
    long i = (long)blockIdx.x * blockDim.x + threadIdx.x;
    if (i >= (long)BB * HH * TT) return;
    int t = i & (TT - 1);
    long r = i >> 8;
    int h = r & (HH - 1);
    int b = (int)(r >> 11);
    hsT[i] = hs[(size_t)t * (BB * HH) + (size_t)b * HH + h];
}

// ---------------------------------------------------------------------------
// Host driver
// ---------------------------------------------------------------------------
extern "C" void kernel_launch(void* const* d_in, const int* in_sizes, int n_in,
                              void* d_out, int out_size) {
    const int*   ids  = (const int*)d_in[0];
    const float* h0   = (const float*)d_in[1];
    const float* c0   = (const float*)d_in[2];
    const float* embW = (const float*)d_in[3];
    const float* Wih  = (const float*)d_in[4];
    const float* Whh  = (const float*)d_in[5];
    const float* bvec = (const float*)d_in[6];
    const float* Watt = (const float*)d_in[7];
    const float* batt = (const float*)d_in[8];
    const float* decW = (const float*)d_in[9];
    const float* decb = (const float*)d_in[10];
    float* out = (float*)d_out;

    __half *wih16, *whh16, *watt16, *decw16, *x16, *hs16, *h016, *attn16, *hsT16, *ctx16, *att16;
    float *gin, *scores, *ctx32, *att32;
    unsigned *barc, *barg;
    cudaGetSymbolAddress((void**)&wih16,  g_wih16);
    cudaGetSymbolAddress((void**)&whh16,  g_whh16);
    cudaGetSymbolAddress((void**)&watt16, g_watt16);
    cudaGetSymbolAddress((void**)&decw16, g_decw16);
    cudaGetSymbolAddress((void**)&x16,    g_x16);
    cudaGetSymbolAddress((void**)&gin,    g_gin);
    cudaGetSymbolAddress((void**)&hs16,   g_hs16);
    cudaGetSymbolAddress((void**)&h016,   g_h0_16);
    cudaGetSymbolAddress((void**)&scores, g_scores);
    cudaGetSymbolAddress((void**)&attn16, g_attn16);
    cudaGetSymbolAddress((void**)&hsT16,  g_hsT16);
    cudaGetSymbolAddress((void**)&ctx32,  g_ctx32);
    cudaGetSymbolAddress((void**)&ctx16,  g_ctx16);
    cudaGetSymbolAddress((void**)&att32,  g_att32);
    cudaGetSymbolAddress((void**)&att16,  g_att16);
    cudaGetSymbolAddress((void**)&barc,   g_bar_cnt);
    cudaGetSymbolAddress((void**)&barg,   g_bar_gen);

    cudaFuncSetAttribute(gemm_tc<true,  false, false>, cudaFuncAttributeMaxDynamicSharedMemorySize, GEMM_SMEM);
    cudaFuncSetAttribute(gemm_tc<false, false, false>, cudaFuncAttributeMaxDynamicSharedMemorySize, GEMM_SMEM);
    cudaFuncSetAttribute(gemm_tc<true,  true,  true >, cudaFuncAttributeMaxDynamicSharedMemorySize, GEMM_SMEM);
    cudaFuncSetAttribute(lstm_layer_persist, cudaFuncAttributeMaxDynamicSharedMemorySize, LSTM_SMEM);

    const long nWih = (long)LL * H4 * HH;
    const long nWatt = (long)HH * 2 * HH;
    const long nDec = (long)VV * HH;

    f32_to_f16<<<(unsigned)(nWih / 1024), 256>>>(Wih,  wih16, nWih);
    f32_to_f16<<<(unsigned)(nWih / 1024), 256>>>(Whh,  whh16, nWih);
    f32_to_f16<<<(unsigned)(nWatt / 1024), 256>>>(Watt, watt16, nWatt);
    f32_to_f16<<<(unsigned)(nDec / 1024), 256>>>(decW, decw16, nDec);

    embed_gather<<<TB, 256>>>(ids, embW, x16);

    const long layerW = (long)H4 * HH;

    for (int l = 0; l < LL; l++) {
        const __half* xin = (l == 0) ? x16 : hs16;
        gemm_tc<true, false, false><<<dim3(H4 / 128, TB / 128, 1), 256, GEMM_SMEM>>>(
            gin, xin, wih16 + (size_t)l * layerW, bvec + (size_t)l * H4,
            TB, H4, HH, HH, HH, H4, 0, 0, 0);
        lstm_layer_persist<<<NCTA, 256, LSTM_SMEM>>>(
            h0 + (size_t)l * BB * HH, c0 + (size_t)l * BB * HH,
            gin, whh16 + (size_t)l * layerW, hs16, h016, barc, barg);
    }

    gemm_tc<false, false, false><<<dim3(2, 2, BB), 256, GEMM_SMEM>>>(
        scores, hs16, hs16, nullptr,
        TT, TT, HH, (long)BB * HH, (long)BB * HH, (long)BB * TT,
        HH, HH, TT);

    softmax_causal<<<TB, 256>>>(scores, attn16);

    transpose_hs<<<(unsigned)((long)BB * HH * TT / 256), 256>>>(hs16, hsT16);

    gemm_tc<false, false, false><<<dim3(HH / 128, 2, BB), 256, GEMM_SMEM>>>(
        ctx32, attn16, hsT16, nullptr,
        TT, HH, TT, (long)BB * TT, TT, (long)BB * HH,
        TT, (long)HH * TT, HH);

    f32_to_f16<<<(unsigned)((long)TB * HH / 1024), 256>>>(ctx32, ctx16, (long)TB * HH);

    gemm_tc<false, false, false><<<dim3(HH / 128, TB / 128, 1), 256, GEMM_SMEM>>>(
        att32, hs16, watt16, nullptr,
        TB, HH, HH, HH, 2 * HH, HH, 0, 0, 0);
    gemm_tc<true, true, true><<<dim3(HH / 128, TB / 128, 1), 256, GEMM_SMEM>>>(
        att32, ctx16, watt16 + HH, batt,
        TB, HH, HH, HH, 2 * HH, HH, 0, 0, 0);

    f32_to_f16<<<(unsigned)((long)TB * HH / 1024), 256>>>(att32, att16, (long)TB * HH);

    gemm_tc<true, false, false><<<dim3(VV / 128, TB / 128, 1), 256, GEMM_SMEM>>>(
        out, att16, decw16, decb,
        TB, VV, HH, HH, HH, VV, 0, 0, 0);
}